// round 5
// baseline (speedup 1.0000x reference)
#include <cuda_runtime.h>
#include <cuda_bf16.h>
#include <cstdint>

#define Bsz 16
#define Ssz 64
#define Esz 256
#define Hsz 256
#define Msz (Bsz*Ssz)   /* 1024 flattened (b,s) rows */
#define G4H 1024        /* 4*H gate rows */

// ---------------------------------------------------------------------------
// Global scratch (no allocations allowed)
// ---------------------------------------------------------------------------
__device__ float g_emb[Msz*Esz];      // emb[b,s,:]
__device__ float g_G1 [Msz*G4H];      // emb@W_ih^T + (b_ih+b_hh)
__device__ float g_Ex [Msz*G4H];      // emb@Wx^T + b_cell
__device__ float g_shared[Msz*Hsz];   // pass-1 hidden states
__device__ float g_A  [Msz*Hsz];      // shared@Ws1^T + emb@Ws3^T + Ws_b
__device__ float g_SWm[Msz*G4H];      // shared@Wm^T

// ---------------------------------------------------------------------------
// Helpers
// ---------------------------------------------------------------------------
__device__ __forceinline__ float tanha(float x){
  float r; asm("tanh.approx.f32 %0, %1;" : "=f"(r) : "f"(x)); return r;
}
// sigmoid via tanh.approx: sig(x) = 0.5*tanh(x/2) + 0.5   (abs err ~1e-5)
__device__ __forceinline__ float sigt(float x){
  return fmaf(0.5f, tanha(0.5f*x), 0.5f);
}
__device__ __forceinline__ void cluster_sync_(){
  asm volatile("barrier.cluster.arrive.aligned;" ::: "memory");
  asm volatile("barrier.cluster.wait.aligned;"   ::: "memory");
}
// store one float into the same smem offset of cluster CTA `rk`
__device__ __forceinline__ void st_peer(void* lp, int rk, float v){
  uint32_t la = (uint32_t)__cvta_generic_to_shared(lp);
  uint32_t ra;
  asm volatile("mapa.shared::cluster.u32 %0, %1, %2;" : "=r"(ra) : "r"(la), "r"(rk));
  asm volatile("st.shared::cluster.f32 [%0], %1;" :: "r"(ra), "f"(v) : "memory");
}
// arrive (release, cluster scope) on peer rk's mbarrier at the same offset
__device__ __forceinline__ void mbar_arrive_peer(void* lp, int rk){
  uint32_t la = (uint32_t)__cvta_generic_to_shared(lp);
  uint32_t ra;
  asm volatile("mapa.shared::cluster.u32 %0, %1, %2;" : "=r"(ra) : "r"(la), "r"(rk));
  asm volatile("mbarrier.arrive.release.cluster.shared::cluster.b64 _, [%0];"
               :: "r"(ra) : "memory");
}
__device__ __forceinline__ void mbar_init(void* lp, uint32_t cnt){
  uint32_t la = (uint32_t)__cvta_generic_to_shared(lp);
  asm volatile("mbarrier.init.shared.b64 [%0], %1;" :: "r"(la), "r"(cnt) : "memory");
}
// acquire-cluster wait on local mbarrier for the given phase parity
__device__ __forceinline__ void mbar_wait(void* lp, uint32_t parity){
  uint32_t la = (uint32_t)__cvta_generic_to_shared(lp);
  uint32_t done;
  asm volatile(
    "{\n\t.reg .pred p;\n\t"
    "mbarrier.try_wait.parity.acquire.cluster.shared::cta.b64 p, [%1], %2;\n\t"
    "selp.b32 %0, 1, 0, p;\n\t}"
    : "=r"(done) : "r"(la), "r"(parity) : "memory");
  while(!done){
    asm volatile(
      "{\n\t.reg .pred p;\n\t"
      "mbarrier.try_wait.parity.acquire.cluster.shared::cta.b64 p, [%1], %2, 0x989680;\n\t"
      "selp.b32 %0, 1, 0, p;\n\t}"
      : "=r"(done) : "r"(la), "r"(parity) : "memory");
  }
}

// ---------------------------------------------------------------------------
// K0: embedding gather.  grid = 1024 blocks, 64 threads (one float4 each)
// ---------------------------------------------------------------------------
__global__ void k_gather(const int* __restrict__ x, const float* __restrict__ embed){
  int m = blockIdx.x;
  int v = x[m];
  const float4* s = (const float4*)(embed + (size_t)v*Esz);
  float4* d = (float4*)(g_emb + (size_t)m*Esz);
  d[threadIdx.x] = s[threadIdx.x];
}

// ---------------------------------------------------------------------------
// K1: generic tiled GEMM  C[m][n] = X[m]·W[n] (+bias1+bias2)
//   mode 0: G1 = emb@W_ih^T       mode 1: Ex = emb@Wx^T
//   mode 2: SWm = shared@Wm^T     mode 3: A = shared@Ws1^T + emb@Ws3^T
// 64x64 tile, BK=16, 256 threads, 4x4 micro-tile.
// ---------------------------------------------------------------------------
__global__ void __launch_bounds__(256) k_gemm(
    int mode, const float* __restrict__ W, const float* __restrict__ b1,
    const float* __restrict__ b2, int N, int K, int Ksplit, int ldw, int wskip)
{
  const float* X1 = (mode >= 2) ? g_shared : g_emb;
  const float* X2 = g_emb;
  float* C = (mode==0) ? g_G1 : (mode==1) ? g_Ex : (mode==2) ? g_SWm : g_A;

  __shared__ __align__(16) float Xs[16][68];
  __shared__ __align__(16) float Ws[16][68];

  int tid = threadIdx.x;
  int m0 = blockIdx.x*64, n0 = blockIdx.y*64;
  int lr = tid>>2, lc = tid&3;
  int tx = tid&15, ty = tid>>4;

  float acc[4][4];
  #pragma unroll
  for(int i=0;i<4;i++){
    #pragma unroll
    for(int j=0;j<4;j++) acc[i][j]=0.f;
  }

  for(int kt=0; kt<K; kt+=16){
    const float* xsrc = (kt < Ksplit)
        ? (X1 + (size_t)(m0+lr)*Esz + kt)
        : (X2 + (size_t)(m0+lr)*Esz + (kt-Ksplit));
    float4 xv = *(const float4*)(xsrc + lc*4);
    int kcol = kt + lc*4;
    int wc = (kcol < Ksplit) ? kcol : kcol + wskip;
    float4 wv = *(const float4*)(W + (size_t)(n0+lr)*ldw + wc);

    __syncthreads();
    Xs[lc*4+0][lr]=xv.x; Xs[lc*4+1][lr]=xv.y; Xs[lc*4+2][lr]=xv.z; Xs[lc*4+3][lr]=xv.w;
    Ws[lc*4+0][lr]=wv.x; Ws[lc*4+1][lr]=wv.y; Ws[lc*4+2][lr]=wv.z; Ws[lc*4+3][lr]=wv.w;
    __syncthreads();

    #pragma unroll
    for(int k=0;k<16;k++){
      float4 a  = *(const float4*)&Xs[k][ty*4];
      float4 bb = *(const float4*)&Ws[k][tx*4];
      acc[0][0]+=a.x*bb.x; acc[0][1]+=a.x*bb.y; acc[0][2]+=a.x*bb.z; acc[0][3]+=a.x*bb.w;
      acc[1][0]+=a.y*bb.x; acc[1][1]+=a.y*bb.y; acc[1][2]+=a.y*bb.z; acc[1][3]+=a.y*bb.w;
      acc[2][0]+=a.z*bb.x; acc[2][1]+=a.z*bb.y; acc[2][2]+=a.z*bb.z; acc[2][3]+=a.z*bb.w;
      acc[3][0]+=a.w*bb.x; acc[3][1]+=a.w*bb.y; acc[3][2]+=a.w*bb.z; acc[3][3]+=a.w*bb.w;
    }
  }

  #pragma unroll
  for(int j=0;j<4;j++){
    int n = n0 + tx*4 + j;
    float bias = (b1 ? b1[n] : 0.f) + (b2 ? b2[n] : 0.f);
    #pragma unroll
    for(int i=0;i<4;i++)
      C[(size_t)(m0+ty*4+i)*N + n] = acc[i][j] + bias;
  }
}

// ---------------------------------------------------------------------------
// K2: pass-1 shared LSTM.  Cluster of 8 CTAs per batch element, 512 threads.
// CTA r owns h-indices [32r,32r+32) => 128 gate rows.
// Thread: rq = tid>>4 (row in slice), cc = tid&15 (16-wide k-chunk).
// W_hh rows in registers w[4][16].  Step handoff: producers (cc==0) store
// h to all 8 peers + arrive on each peer's mbarrier (256 arrivals/phase);
// consumers try_wait (acquire.cluster) on the LOCAL mbarrier. No
// barrier.cluster in the loop -> no CCTL.IVALL, no 8-SM broadcast barrier.
// ---------------------------------------------------------------------------
__global__ void __cluster_dims__(8,1,1) __launch_bounds__(512,1)
k_pass1(const float* __restrict__ W_hh)
{
  __shared__ float sh[2][Hsz];
  __shared__ __align__(8) unsigned long long mb_h;

  int b = blockIdx.x >> 3, r = blockIdx.x & 7;
  int tid = threadIdx.x;
  int rq = tid >> 4, cc = tid & 15;
  int gidx = r*32 + rq;

  float w[4][16];
  #pragma unroll
  for(int q=0;q<4;q++){
    const float4* src = (const float4*)(W_hh + (size_t)(q*Hsz + gidx)*Hsz + cc*16);
    #pragma unroll
    for(int kk=0;kk<4;kk++){
      float4 v = src[kk];
      w[q][kk*4+0]=v.x; w[q][kk*4+1]=v.y; w[q][kk*4+2]=v.z; w[q][kk*4+3]=v.w;
    }
  }
  if(tid < Hsz) sh[0][tid] = 0.f;
  if(tid == 0) mbar_init(&mb_h, 256);
  float c = 0.f;
  __syncthreads();
  cluster_sync_();   // mbarrier + sh[0] visible cluster-wide before any arrive

  const float* __restrict__ G1b = g_G1 + (size_t)b*Ssz*G4H + gidx;

  for(int t=0;t<Ssz;t++){
    if(t>0) mbar_wait(&mb_h, (t-1)&1);   // h(t) landed in sh[t&1]

    float e0,e1,e2,e3;
    if(cc==0){
      const float* p = G1b + (size_t)t*G4H;
      e0 = p[0]; e1 = p[256]; e2 = p[512]; e3 = p[768];
    }
    const float* hk = sh[t&1] + cc*16;
    float a0=0.f,a1=0.f,a2=0.f,a3=0.f;
    #pragma unroll
    for(int k=0;k<16;k++){
      float hv = hk[k];
      a0 += w[0][k]*hv; a1 += w[1][k]*hv; a2 += w[2][k]*hv; a3 += w[3][k]*hv;
    }
    #pragma unroll
    for(int m=1;m<16;m<<=1){
      a0 += __shfl_xor_sync(0xffffffffu,a0,m);
      a1 += __shfl_xor_sync(0xffffffffu,a1,m);
      a2 += __shfl_xor_sync(0xffffffffu,a2,m);
      a3 += __shfl_xor_sync(0xffffffffu,a3,m);
    }
    if(cc==0){
      float gi = a0 + e0, gf = a1 + e1, gg = a2 + e2, go = a3 + e3;
      c = sigt(gf)*c + sigt(gi)*tanha(gg);
      float h = sigt(go)*tanha(c);
      int p1 = (t+1)&1;
      #pragma unroll
      for(int rk=0;rk<8;rk++) st_peer(&sh[p1][gidx], rk, h);
      #pragma unroll
      for(int rk=0;rk<8;rk++) mbar_arrive_peer(&mb_h, rk);
      g_shared[(size_t)(b*Ssz+t)*Hsz + gidx] = h;
    }
  }
  cluster_sync_();   // drain in-flight remote ops before any CTA exits
}

// ---------------------------------------------------------------------------
// K4: pass-2 task LSTM with attention.  Cluster 8, 512 threads.
// Three mbarrier-mediated exchanges per step (hW2: 256 arrivals,
// Si: 64 arrivals, h: 256 arrivals) + one local __syncthreads for softmax.
// ---------------------------------------------------------------------------
__global__ void __cluster_dims__(8,1,1) __launch_bounds__(512,1)
k_pass2(const float* __restrict__ Wh,   const float* __restrict__ Ws_w,
        const float* __restrict__ Us_w, const float* __restrict__ Us_b,
        const float* __restrict__ fc_w, const float* __restrict__ fc_b,
        const int*   __restrict__ mask, float* __restrict__ out)
{
  __shared__ __align__(16) float sSWm[128*64];  // [q*32+rq][s]  32 KB
  __shared__ float sA[8*Hsz];
  __shared__ float sUs[Hsz];
  __shared__ float sh[2][Hsz];
  __shared__ float shW2[Hsz];
  __shared__ float sSi[Ssz];
  __shared__ float sAtt[Ssz];
  __shared__ int   sValid[Ssz];
  __shared__ __align__(8) unsigned long long mb_h, mb_w2, mb_si;

  int b = blockIdx.x >> 3, r = blockIdx.x & 7;
  int tid = threadIdx.x;
  int rq = tid >> 4, cc = tid & 15;
  int lane = tid & 31, wid = tid >> 5;
  int gidx = r*32 + rq;

  for(int idx=tid; idx<128*64; idx+=512){
    int row = idx >> 6, s = idx & 63;
    sSWm[idx] = g_SWm[(size_t)(b*Ssz+s)*G4H + (row>>5)*Hsz + r*32 + (row&31)];
  }
  for(int idx=tid; idx<8*Hsz; idx+=512)
    sA[idx] = g_A[(size_t)(b*Ssz + r*8 + (idx>>8))*Hsz + (idx&255)];
  if(tid < Hsz) sUs[tid] = Us_w[tid];
  if(tid < Ssz) sValid[tid] = mask[b*Ssz + tid];
  if(tid < Hsz) sh[0][tid] = 0.f;
  if(tid == 0){
    mbar_init(&mb_h, 256);
    mbar_init(&mb_w2, 256);
    mbar_init(&mb_si, 64);
  }

  float w[4][16];
  #pragma unroll
  for(int q=0;q<4;q++){
    const float4* src = (const float4*)(Wh + (size_t)(q*Hsz + gidx)*Hsz + cc*16);
    #pragma unroll
    for(int kk=0;kk<4;kk++){
      float4 v=src[kk];
      w[q][kk*4+0]=v.x; w[q][kk*4+1]=v.y; w[q][kk*4+2]=v.z; w[q][kk*4+3]=v.w;
    }
  }
  float sw2[16];
  {
    const float4* src = (const float4*)(Ws_w + (size_t)gidx*768 + Hsz + cc*16);
    #pragma unroll
    for(int kk=0;kk<4;kk++){
      float4 v=src[kk];
      sw2[kk*4+0]=v.x; sw2[kk*4+1]=v.y; sw2[kk*4+2]=v.z; sw2[kk*4+3]=v.w;
    }
  }
  float usb = Us_b[0];
  float c = 0.f;
  __syncthreads();
  cluster_sync_();   // mbarriers + sh[0] visible cluster-wide

  const float* __restrict__ Exb = g_Ex + (size_t)b*Ssz*G4H + gidx;

  for(int t=0;t<Ssz;t++){
    if(t>0) mbar_wait(&mb_h, (t-1)&1);   // h(t) landed in sh[t&1]

    float e0,e1,e2,e3;
    if(cc==0){
      const float* p = Exb + (size_t)t*G4H;
      e0 = p[0]; e1 = p[256]; e2 = p[512]; e3 = p[768];
    }

    // (a) Ws2·h and Wh·h dots against current h
    const float* hk = sh[t&1] + cc*16;
    float pw=0.f, a0=0.f,a1=0.f,a2=0.f,a3=0.f;
    #pragma unroll
    for(int k=0;k<16;k++){
      float hv = hk[k];
      pw += sw2[k]*hv;
      a0 += w[0][k]*hv; a1 += w[1][k]*hv; a2 += w[2][k]*hv; a3 += w[3][k]*hv;
    }
    #pragma unroll
    for(int m=1;m<16;m<<=1){
      pw += __shfl_xor_sync(0xffffffffu,pw,m);
      a0 += __shfl_xor_sync(0xffffffffu,a0,m);
      a1 += __shfl_xor_sync(0xffffffffu,a1,m);
      a2 += __shfl_xor_sync(0xffffffffu,a2,m);
      a3 += __shfl_xor_sync(0xffffffffu,a3,m);
    }
    if(cc==0){
      #pragma unroll
      for(int rk=0;rk<8;rk++) st_peer(&shW2[gidx], rk, pw);
      #pragma unroll
      for(int rk=0;rk<8;rk++) mbar_arrive_peer(&mb_w2, rk);
    }
    mbar_wait(&mb_w2, t&1);

    // (b) Si for this CTA's 8 s values (warps 0-7)
    if(wid < 8){
      float sacc = 0.f;
      #pragma unroll
      for(int jj=0;jj<8;jj++){
        int j = jj*32 + lane;
        sacc += sUs[j]*tanha(sA[wid*Hsz + j] + shW2[j]);
      }
      #pragma unroll
      for(int m=16;m>=1;m>>=1) sacc += __shfl_xor_sync(0xffffffffu,sacc,m);
      if(lane==0){
        int s = r*8 + wid;
        float v = sacc + usb;
        #pragma unroll
        for(int rk=0;rk<8;rk++) st_peer(&sSi[s], rk, v);
        #pragma unroll
        for(int rk=0;rk<8;rk++) mbar_arrive_peer(&mb_si, rk);
      }
    }
    mbar_wait(&mb_si, t&1);

    // (c) masked softmax over S (warp 0), local barrier publishes sAtt
    if(wid==0){
      float v0 = sValid[lane]    ? sSi[lane]    : -1e9f;
      float v1 = sValid[lane+32] ? sSi[lane+32] : -1e9f;
      float mx = fmaxf(v0,v1);
      #pragma unroll
      for(int m=16;m>=1;m>>=1) mx = fmaxf(mx, __shfl_xor_sync(0xffffffffu,mx,m));
      float x0 = __expf(v0-mx), x1 = __expf(v1-mx);
      float sm = x0+x1;
      #pragma unroll
      for(int m=16;m>=1;m>>=1) sm += __shfl_xor_sync(0xffffffffu,sm,m);
      float inv = __fdividef(1.f, sm);
      sAtt[lane]    = x0*inv;
      sAtt[lane+32] = x1*inv;
    }
    __syncthreads();

    // (d) att·SWm + gates
    {
      const float4 av = *(const float4*)&sAtt[cc*4];
      float b0,b1,b2,b3;
      {
        float4 v = *(const float4*)&sSWm[(0*32+rq)*64 + cc*4];
        b0 = v.x*av.x + v.y*av.y + v.z*av.z + v.w*av.w;
      }
      {
        float4 v = *(const float4*)&sSWm[(1*32+rq)*64 + cc*4];
        b1 = v.x*av.x + v.y*av.y + v.z*av.z + v.w*av.w;
      }
      {
        float4 v = *(const float4*)&sSWm[(2*32+rq)*64 + cc*4];
        b2 = v.x*av.x + v.y*av.y + v.z*av.z + v.w*av.w;
      }
      {
        float4 v = *(const float4*)&sSWm[(3*32+rq)*64 + cc*4];
        b3 = v.x*av.x + v.y*av.y + v.z*av.z + v.w*av.w;
      }
      #pragma unroll
      for(int m=1;m<16;m<<=1){
        b0 += __shfl_xor_sync(0xffffffffu,b0,m);
        b1 += __shfl_xor_sync(0xffffffffu,b1,m);
        b2 += __shfl_xor_sync(0xffffffffu,b2,m);
        b3 += __shfl_xor_sync(0xffffffffu,b3,m);
      }
      if(cc==0){
        float gi = a0 + b0 + e0;
        float gf = a1 + b1 + e1;
        float gg = a2 + b2 + e2;
        float go = a3 + b3 + e3;
        c = sigt(gf)*c + sigt(gi)*tanha(gg);
        float h = sigt(go)*tanha(c);
        int p1 = (t+1)&1;
        #pragma unroll
        for(int rk=0;rk<8;rk++) st_peer(&sh[p1][gidx], rk, h);
        #pragma unroll
        for(int rk=0;rk<8;rk++) mbar_arrive_peer(&mb_h, rk);
      }
    }
  }

  mbar_wait(&mb_h, (Ssz-1)&1);   // h(64) landed in sh[0]

  // final classifier: out[b] = sigmoid(h·fc_w + fc_b)
  if(r==0 && wid==0){
    float acc = 0.f;
    #pragma unroll
    for(int jj=0;jj<8;jj++){ int j=jj*32+lane; acc += fc_w[j]*sh[0][j]; }
    #pragma unroll
    for(int m=16;m>=1;m>>=1) acc += __shfl_xor_sync(0xffffffffu,acc,m);
    if(lane==0) out[b] = sigt(acc + fc_b[0]);
  }
  cluster_sync_();   // drain in-flight remote ops before any CTA exits
}

// ---------------------------------------------------------------------------
// Launch
// ---------------------------------------------------------------------------
extern "C" void kernel_launch(void* const* d_in, const int* in_sizes, int n_in,
                              void* d_out, int out_size)
{
  const int* x    = (const int*)d_in[0];
  const int* mask = (const int*)d_in[1];
  int base = (in_sizes[2] == 1) ? 3 : 2;   // skip scalar TASK if present
  const float* embed  = (const float*)d_in[base+0];
  const float* W_ih   = (const float*)d_in[base+1];
  const float* W_hh   = (const float*)d_in[base+2];
  const float* b_ih   = (const float*)d_in[base+3];
  const float* b_hh   = (const float*)d_in[base+4];
  const float* Ws_w   = (const float*)d_in[base+5];
  const float* Ws_b   = (const float*)d_in[base+6];
  const float* Us_w   = (const float*)d_in[base+7];
  const float* Us_b   = (const float*)d_in[base+8];
  const float* Wx     = (const float*)d_in[base+9];
  const float* Wh     = (const float*)d_in[base+10];
  const float* Wm     = (const float*)d_in[base+11];
  const float* b_cell = (const float*)d_in[base+12];
  const float* fc_w   = (const float*)d_in[base+13];
  const float* fc_b   = (const float*)d_in[base+14];
  float* out = (float*)d_out;
  (void)n_in; (void)out_size;

  k_gather<<<Msz, 64>>>(x, embed);
  k_gemm<<<dim3(16,16), 256>>>(0, W_ih, b_ih, b_hh, G4H, 256, 256, 256, 0);
  k_gemm<<<dim3(16,16), 256>>>(1, Wx,   b_cell, nullptr, G4H, 256, 256, 256, 0);
  k_pass1<<<128, 512>>>(W_hh);
  k_gemm<<<dim3(16,16), 256>>>(2, Wm,   nullptr, nullptr, G4H, 256, 256, 256, 0);
  k_gemm<<<dim3(16,4),  256>>>(3, Ws_w, Ws_b,   nullptr, Hsz, 512, 256, 768, 256);
  k_pass2<<<128, 512>>>(Wh, Ws_w, Us_w, Us_b, fc_w, fc_b, mask, out);
}

// round 7
// speedup vs baseline: 1.5917x; 1.5917x over previous
#include <cuda_runtime.h>
#include <cuda_bf16.h>
#include <cstdint>

#define Bsz 16
#define Ssz 64
#define Esz 256
#define Hsz 256
#define Msz (Bsz*Ssz)   /* 1024 flattened (b,s) rows */
#define G4H 1024        /* 4*H gate rows */

typedef unsigned long long ull;

// ---------------------------------------------------------------------------
// Global scratch (no allocations allowed)
// ---------------------------------------------------------------------------
__device__ float g_emb[Msz*Esz];      // emb[b,s,:]
__device__ float g_G1 [Msz*G4H];      // emb@W_ih^T + (b_ih+b_hh)
__device__ float g_Ex [Msz*G4H];      // emb@Wx^T + b_cell
__device__ float g_shared[Msz*Hsz];   // pass-1 hidden states
__device__ float g_A  [Msz*Hsz];      // shared@Ws1^T + emb@Ws3^T + Ws_b
__device__ float g_SWm[Msz*G4H];      // shared@Wm^T

// ---------------------------------------------------------------------------
// Helpers
// ---------------------------------------------------------------------------
__device__ __forceinline__ float tanha(float x){
  float r; asm("tanh.approx.f32 %0, %1;" : "=f"(r) : "f"(x)); return r;
}
__device__ __forceinline__ float sigt(float x){          // sigmoid via tanh
  return fmaf(0.5f, tanha(0.5f*x), 0.5f);
}
__device__ __forceinline__ void cluster_sync_(){
  asm volatile("barrier.cluster.arrive.aligned;" ::: "memory");
  asm volatile("barrier.cluster.wait.aligned;"   ::: "memory");
}
__device__ __forceinline__ void st_peer(void* lp, int rk, float v){
  uint32_t la = (uint32_t)__cvta_generic_to_shared(lp);
  uint32_t ra;
  asm volatile("mapa.shared::cluster.u32 %0, %1, %2;" : "=r"(ra) : "r"(la), "r"(rk));
  asm volatile("st.shared::cluster.f32 [%0], %1;" :: "r"(ra), "f"(v) : "memory");
}
__device__ __forceinline__ ull pk2(float lo, float hi){
  ull r; asm("mov.b64 %0, {%1,%2};" : "=l"(r) : "f"(lo), "f"(hi)); return r;
}
__device__ __forceinline__ void fma2(ull& acc, ull a, ull b){
  asm("fma.rn.f32x2 %0, %1, %2, %0;" : "+l"(acc) : "l"(a), "l"(b));
}
__device__ __forceinline__ float sum2(ull a){
  float lo, hi; asm("mov.b64 {%0,%1}, %2;" : "=f"(lo), "=f"(hi) : "l"(a));
  return lo + hi;
}

// ---------------------------------------------------------------------------
// K0: embedding gather.  grid = 1024 blocks, 64 threads (one float4 each)
// ---------------------------------------------------------------------------
__global__ void k_gather(const int* __restrict__ x, const float* __restrict__ embed){
  int m = blockIdx.x;
  int v = x[m];
  const float4* s = (const float4*)(embed + (size_t)v*Esz);
  float4* d = (float4*)(g_emb + (size_t)m*Esz);
  d[threadIdx.x] = s[threadIdx.x];
}

// ---------------------------------------------------------------------------
// K1: generic tiled GEMM (unchanged from R4; verified correct+adequate)
// ---------------------------------------------------------------------------
__global__ void __launch_bounds__(256) k_gemm(
    int mode, const float* __restrict__ W, const float* __restrict__ b1,
    const float* __restrict__ b2, int N, int K, int Ksplit, int ldw, int wskip)
{
  const float* X1 = (mode >= 2) ? g_shared : g_emb;
  const float* X2 = g_emb;
  float* C = (mode==0) ? g_G1 : (mode==1) ? g_Ex : (mode==2) ? g_SWm : g_A;

  __shared__ __align__(16) float Xs[16][68];
  __shared__ __align__(16) float Ws[16][68];

  int tid = threadIdx.x;
  int m0 = blockIdx.x*64, n0 = blockIdx.y*64;
  int lr = tid>>2, lc = tid&3;
  int tx = tid&15, ty = tid>>4;

  float acc[4][4];
  #pragma unroll
  for(int i=0;i<4;i++){
    #pragma unroll
    for(int j=0;j<4;j++) acc[i][j]=0.f;
  }

  for(int kt=0; kt<K; kt+=16){
    const float* xsrc = (kt < Ksplit)
        ? (X1 + (size_t)(m0+lr)*Esz + kt)
        : (X2 + (size_t)(m0+lr)*Esz + (kt-Ksplit));
    float4 xv = *(const float4*)(xsrc + lc*4);
    int kcol = kt + lc*4;
    int wc = (kcol < Ksplit) ? kcol : kcol + wskip;
    float4 wv = *(const float4*)(W + (size_t)(n0+lr)*ldw + wc);

    __syncthreads();
    Xs[lc*4+0][lr]=xv.x; Xs[lc*4+1][lr]=xv.y; Xs[lc*4+2][lr]=xv.z; Xs[lc*4+3][lr]=xv.w;
    Ws[lc*4+0][lr]=wv.x; Ws[lc*4+1][lr]=wv.y; Ws[lc*4+2][lr]=wv.z; Ws[lc*4+3][lr]=wv.w;
    __syncthreads();

    #pragma unroll
    for(int k=0;k<16;k++){
      float4 a  = *(const float4*)&Xs[k][ty*4];
      float4 bb = *(const float4*)&Ws[k][tx*4];
      acc[0][0]+=a.x*bb.x; acc[0][1]+=a.x*bb.y; acc[0][2]+=a.x*bb.z; acc[0][3]+=a.x*bb.w;
      acc[1][0]+=a.y*bb.x; acc[1][1]+=a.y*bb.y; acc[1][2]+=a.y*bb.z; acc[1][3]+=a.y*bb.w;
      acc[2][0]+=a.z*bb.x; acc[2][1]+=a.z*bb.y; acc[2][2]+=a.z*bb.z; acc[2][3]+=a.z*bb.w;
      acc[3][0]+=a.w*bb.x; acc[3][1]+=a.w*bb.y; acc[3][2]+=a.w*bb.z; acc[3][3]+=a.w*bb.w;
    }
  }

  #pragma unroll
  for(int j=0;j<4;j++){
    int n = n0 + tx*4 + j;
    float bias = (b1 ? b1[n] : 0.f) + (b2 ? b2[n] : 0.f);
    #pragma unroll
    for(int i=0;i<4;i++)
      C[(size_t)(m0+ty*4+i)*N + n] = acc[i][j] + bias;
  }
}

// ---------------------------------------------------------------------------
// K2: pass-1 shared LSTM.  Cluster of 8 CTAs; FOUR batch elements/cluster.
// grid = 32 CTAs (4 clusters).  CTA r owns h-indices [32r,32r+32).
// Thread layout: gs = tid>>8 (gate-plane: gates {0,1} or {2,3}),
//                rq = (tid>>3)&31 (row in slice), cc = tid&7 (32-wide k chunk).
// W_hh slice in registers as packed f32x2 pairs (w0/w1: 2 gates x 32 k).
// Per step: 4 batches' dots (f32x2), 3-level shfl reduce, local smem gate
// handoff, 32 producer threads do activations for all 4 batches, DSMEM h
// broadcast, ONE cluster barrier.
// ---------------------------------------------------------------------------
__global__ void __cluster_dims__(8,1,1) __launch_bounds__(512,1)
k_pass1(const float* __restrict__ W_hh)
{
  __shared__ float sh[4][2][Hsz];    // [batch][parity][h]  8 KB
  __shared__ float sGr[4][4][32];    // [batch][gate][row]  2 KB

  int cl = blockIdx.x >> 3, r = blockIdx.x & 7;
  int b0 = cl*4;
  int tid = threadIdx.x;
  int gs = tid >> 8;
  int rq = (tid >> 3) & 31;
  int cc = tid & 7;
  int gidx = r*32 + rq;
  int q0 = gs*2, q1 = gs*2 + 1;

  ull w0[16], w1[16];
  {
    const float4* s0 = (const float4*)(W_hh + (size_t)(q0*Hsz + gidx)*Hsz + cc*32);
    const float4* s1 = (const float4*)(W_hh + (size_t)(q1*Hsz + gidx)*Hsz + cc*32);
    #pragma unroll
    for(int i=0;i<8;i++){
      float4 a = s0[i]; w0[2*i] = pk2(a.x,a.y); w0[2*i+1] = pk2(a.z,a.w);
      float4 b = s1[i]; w1[2*i] = pk2(b.x,b.y); w1[2*i+1] = pk2(b.z,b.w);
    }
  }
  for(int i=tid; i<4*Hsz; i+=512){ sh[i>>8][0][i&255] = 0.f; }
  float cst[4] = {0.f,0.f,0.f,0.f};
  __syncthreads();
  cluster_sync_();   // peers' sh[*][0] initialized before anyone reads

  for(int t=0;t<Ssz;t++){
    int par = t&1;

    // prefetch gate-input terms for the 4 batches (producers only)
    float e[4][4];
    if(tid < 32){
      #pragma unroll
      for(int g=0; g<4; g++){
        const float* p = g_G1 + (size_t)((b0+g)*Ssz+t)*G4H + r*32 + tid;
        e[g][0]=p[0]; e[g][1]=p[256]; e[g][2]=p[512]; e[g][3]=p[768];
      }
    }

    // dots for 4 batches, 2 gates each (packed f32x2)
    float s0[4], s1[4];
    #pragma unroll
    for(int g=0; g<4; g++){
      const float4* hp = (const float4*)&sh[g][par][cc*32];
      ull a0 = 0ull, a1 = 0ull;
      #pragma unroll
      for(int i=0;i<8;i++){
        float4 hv = hp[i];
        ull h01 = pk2(hv.x,hv.y), h23 = pk2(hv.z,hv.w);
        fma2(a0, w0[2*i], h01); fma2(a0, w0[2*i+1], h23);
        fma2(a1, w1[2*i], h01); fma2(a1, w1[2*i+1], h23);
      }
      s0[g] = sum2(a0); s1[g] = sum2(a1);
    }
    #pragma unroll
    for(int m=1;m<8;m<<=1){
      #pragma unroll
      for(int g=0;g<4;g++){
        s0[g] += __shfl_xor_sync(0xffffffffu, s0[g], m);
        s1[g] += __shfl_xor_sync(0xffffffffu, s1[g], m);
      }
    }
    if(cc==0){
      #pragma unroll
      for(int g=0;g<4;g++){ sGr[g][q0][rq] = s0[g]; sGr[g][q1][rq] = s1[g]; }
    }
    __syncthreads();

    // producers: 32 threads, one row each, all 4 batches
    if(tid < 32){
      int p1 = (t+1)&1;
      int gx = r*32 + tid;
      #pragma unroll
      for(int g=0;g<4;g++){
        float gi = sGr[g][0][tid] + e[g][0];
        float gf = sGr[g][1][tid] + e[g][1];
        float gg = sGr[g][2][tid] + e[g][2];
        float go = sGr[g][3][tid] + e[g][3];
        cst[g] = sigt(gf)*cst[g] + sigt(gi)*tanha(gg);
        float h = sigt(go)*tanha(cst[g]);
        #pragma unroll
        for(int rk=0;rk<8;rk++) st_peer(&sh[g][p1][gx], rk, h);
        g_shared[(size_t)((b0+g)*Ssz+t)*Hsz + gx] = h;
      }
    }
    cluster_sync_();
  }
}

// ---------------------------------------------------------------------------
// K4: pass-2 task LSTM with attention.  Cluster 8; TWO batches/cluster.
// grid = 64 CTAs (8 clusters).  TWO cluster syncs per step:
//   phase a: Ws2·h (local slice!) + Wh·h dots -> local smem hW2 slice
//   phase b: j-slice Si PARTIALS for all 64 s (local A/Us/hW2 slices),
//            all-to-all exchange of 64 partials  [cluster sync #1]
//   phase c: per-CTA Si sum + masked softmax (fully local)
//   phase d: att·SWm + gates -> h broadcast     [cluster sync #2]
// Dynamic smem (~92 KB).
// ---------------------------------------------------------------------------
#define P2_SWM  0            /* [g][128][64]  2*8192  */
#define P2_A    16384        /* [g][64][32]   2*2048  */
#define P2_PART 20480        /* [g][8][64]    2*512   */
#define P2_H    21504        /* [g][2][256]   2*512   */
#define P2_W2   22528        /* [g][32]       2*32    */
#define P2_ATT  22592        /* [g][64]       2*64    */
#define P2_US   22720        /* [32]                  */
#define P2_VAL  22752        /* [g][64] ints  2*64    */
#define P2_FLOATS 22880

__global__ void __cluster_dims__(8,1,1) __launch_bounds__(512,1)
k_pass2(const float* __restrict__ Wh,   const float* __restrict__ Ws_w,
        const float* __restrict__ Us_w, const float* __restrict__ Us_b,
        const float* __restrict__ fc_w, const float* __restrict__ fc_b,
        const int*   __restrict__ mask, float* __restrict__ out)
{
  extern __shared__ __align__(16) float dsm[];
  float* sSWm = dsm + P2_SWM;
  float* sA   = dsm + P2_A;
  float* sPart= dsm + P2_PART;
  float* sh   = dsm + P2_H;
  float* sW2  = dsm + P2_W2;
  float* sAtt = dsm + P2_ATT;
  float* sUs  = dsm + P2_US;
  int*   sVal = (int*)(dsm + P2_VAL);

  int cl = blockIdx.x >> 3, r = blockIdx.x & 7;
  int b0 = cl*2;
  int tid = threadIdx.x;
  int rq = tid >> 4, cc = tid & 15;
  int lane = tid & 31, wid = tid >> 5;
  int gidx = r*32 + rq;

  // prologue loads
  for(int i=tid; i<2*128*64; i+=512){
    int g = i>>13, rem = i & 8191, row = rem>>6, s = rem&63;
    sSWm[i] = g_SWm[(size_t)((b0+g)*Ssz+s)*G4H + (row>>5)*Hsz + r*32 + (row&31)];
  }
  for(int i=tid; i<2*64*32; i+=512){
    int g = i>>11, rem = i & 2047, s = rem>>5, j = rem&31;
    sA[i] = g_A[(size_t)((b0+g)*Ssz+s)*Hsz + r*32 + j];
  }
  if(tid < 32) sUs[tid] = Us_w[r*32 + tid];
  if(tid < 128){ int g = tid>>6; sVal[tid] = mask[(b0+g)*Ssz + (tid&63)]; }
  for(int i=tid; i<2*Hsz; i+=512){ sh[(i>>8)*512 + (i&255)] = 0.f; }  // parity 0

  ull wq[4][8];
  #pragma unroll
  for(int q=0;q<4;q++){
    const float4* src = (const float4*)(Wh + (size_t)(q*Hsz + gidx)*Hsz + cc*16);
    #pragma unroll
    for(int i=0;i<4;i++){
      float4 v = src[i];
      wq[q][2*i] = pk2(v.x,v.y); wq[q][2*i+1] = pk2(v.z,v.w);
    }
  }
  ull w2[8];
  {
    const float4* src = (const float4*)(Ws_w + (size_t)gidx*768 + Hsz + cc*16);
    #pragma unroll
    for(int i=0;i<4;i++){
      float4 v = src[i];
      w2[2*i] = pk2(v.x,v.y); w2[2*i+1] = pk2(v.z,v.w);
    }
  }
  float usb = Us_b[0];
  float cst[2] = {0.f, 0.f};
  __syncthreads();
  cluster_sync_();   // peers' sh init visible

  for(int t=0;t<Ssz;t++){
    int par = t&1;

    // prefetch Ex gate terms (producers)
    float e[2][4];
    if(cc==0){
      #pragma unroll
      for(int g=0;g<2;g++){
        const float* p = g_Ex + (size_t)((b0+g)*Ssz+t)*G4H + gidx;
        e[g][0]=p[0]; e[g][1]=p[256]; e[g][2]=p[512]; e[g][3]=p[768];
      }
    }

    // phase a: Ws2·h (own slice) + Wh·h dots
    float pa[2][4], pp[2];
    #pragma unroll
    for(int g=0;g<2;g++){
      const float4* hp = (const float4*)&sh[g*512 + par*256 + cc*16];
      ull a0=0ull,a1=0ull,a2=0ull,a3=0ull,p=0ull;
      #pragma unroll
      for(int i=0;i<4;i++){
        float4 hv = hp[i];
        ull h01 = pk2(hv.x,hv.y), h23 = pk2(hv.z,hv.w);
        fma2(a0, wq[0][2*i], h01); fma2(a0, wq[0][2*i+1], h23);
        fma2(a1, wq[1][2*i], h01); fma2(a1, wq[1][2*i+1], h23);
        fma2(a2, wq[2][2*i], h01); fma2(a2, wq[2][2*i+1], h23);
        fma2(a3, wq[3][2*i], h01); fma2(a3, wq[3][2*i+1], h23);
        fma2(p,  w2[2*i],    h01); fma2(p,  w2[2*i+1],    h23);
      }
      pa[g][0]=sum2(a0); pa[g][1]=sum2(a1); pa[g][2]=sum2(a2); pa[g][3]=sum2(a3);
      pp[g]=sum2(p);
    }
    #pragma unroll
    for(int m=1;m<16;m<<=1){
      #pragma unroll
      for(int g=0;g<2;g++){
        pp[g]    += __shfl_xor_sync(0xffffffffu, pp[g],    m);
        pa[g][0] += __shfl_xor_sync(0xffffffffu, pa[g][0], m);
        pa[g][1] += __shfl_xor_sync(0xffffffffu, pa[g][1], m);
        pa[g][2] += __shfl_xor_sync(0xffffffffu, pa[g][2], m);
        pa[g][3] += __shfl_xor_sync(0xffffffffu, pa[g][3], m);
      }
    }
    if(cc==0){
      sW2[0*32+rq] = pp[0];
      sW2[1*32+rq] = pp[1];
    }
    __syncthreads();

    // phase b: Si partials over own j-slice, for ALL 64 s
    {
      int sp = tid >> 3, jc = tid & 7;
      float P[2];
      #pragma unroll
      for(int g=0;g<2;g++){
        float acc = 0.f;
        #pragma unroll
        for(int k=0;k<4;k++){
          int j = jc*4 + k;
          acc += sUs[j] * tanha(sA[g*2048 + sp*32 + j] + sW2[g*32 + j]);
        }
        P[g] = acc;
      }
      #pragma unroll
      for(int m=1;m<8;m<<=1){
        P[0] += __shfl_xor_sync(0xffffffffu, P[0], m);
        P[1] += __shfl_xor_sync(0xffffffffu, P[1], m);
      }
      if(jc==0){
        #pragma unroll
        for(int g=0;g<2;g++){
          #pragma unroll
          for(int rk=0;rk<8;rk++) st_peer(&sPart[g*512 + r*64 + sp], rk, P[g]);
        }
      }
    }
    cluster_sync_();   // #1: all partials landed everywhere

    // phase c: Si sum + masked softmax, fully local (warp g handles batch g)
    if(wid < 2){
      int g = wid;
      float t0 = usb, t1 = usb;
      #pragma unroll
      for(int rr=0;rr<8;rr++){
        t0 += sPart[g*512 + rr*64 + lane];
        t1 += sPart[g*512 + rr*64 + lane + 32];
      }
      float v0 = sVal[g*64+lane]    ? t0 : -1e9f;
      float v1 = sVal[g*64+lane+32] ? t1 : -1e9f;
      float mx = fmaxf(v0,v1);
      #pragma unroll
      for(int m=16;m>=1;m>>=1) mx = fmaxf(mx, __shfl_xor_sync(0xffffffffu,mx,m));
      float x0 = __expf(v0-mx), x1 = __expf(v1-mx);
      float sm = x0+x1;
      #pragma unroll
      for(int m=16;m>=1;m>>=1) sm += __shfl_xor_sync(0xffffffffu,sm,m);
      float inv = __fdividef(1.f, sm);
      sAtt[g*64+lane]    = x0*inv;
      sAtt[g*64+lane+32] = x1*inv;
    }
    __syncthreads();

    // phase d: att·SWm + gates + h broadcast
    {
      float pb[2][4];
      #pragma unroll
      for(int g=0;g<2;g++){
        float4 av = *(const float4*)&sAtt[g*64 + cc*4];
        #pragma unroll
        for(int q=0;q<4;q++){
          float4 v = *(const float4*)&sSWm[g*8192 + (q*32+rq)*64 + cc*4];
          pb[g][q] = v.x*av.x + v.y*av.y + v.z*av.z + v.w*av.w;
        }
      }
      #pragma unroll
      for(int m=1;m<16;m<<=1){
        #pragma unroll
        for(int g=0;g<2;g++){
          pb[g][0] += __shfl_xor_sync(0xffffffffu, pb[g][0], m);
          pb[g][1] += __shfl_xor_sync(0xffffffffu, pb[g][1], m);
          pb[g][2] += __shfl_xor_sync(0xffffffffu, pb[g][2], m);
          pb[g][3] += __shfl_xor_sync(0xffffffffu, pb[g][3], m);
        }
      }
      if(cc==0){
        int p1 = (t+1)&1;
        #pragma unroll
        for(int g=0;g<2;g++){
          float gi = pa[g][0] + pb[g][0] + e[g][0];
          float gf = pa[g][1] + pb[g][1] + e[g][1];
          float gg = pa[g][2] + pb[g][2] + e[g][2];
          float go = pa[g][3] + pb[g][3] + e[g][3];
          cst[g] = sigt(gf)*cst[g] + sigt(gi)*tanha(gg);
          float h = sigt(go)*tanha(cst[g]);
          #pragma unroll
          for(int rk=0;rk<8;rk++) st_peer(&sh[g*512 + p1*256 + gidx], rk, h);
        }
      }
    }
    cluster_sync_();   // #2: h(t+1) landed everywhere
  }

  // final classifier (final h is in parity 0 after 64 steps)
  if(r==0 && wid < 2){
    int g = wid;
    float acc = 0.f;
    #pragma unroll
    for(int jj=0;jj<8;jj++) acc += fc_w[jj*32+lane] * sh[g*512 + jj*32 + lane];
    #pragma unroll
    for(int m=16;m>=1;m>>=1) acc += __shfl_xor_sync(0xffffffffu,acc,m);
    if(lane==0) out[b0+g] = sigt(acc + fc_b[0]);
  }
}

// ---------------------------------------------------------------------------
// Launch
// ---------------------------------------------------------------------------
extern "C" void kernel_launch(void* const* d_in, const int* in_sizes, int n_in,
                              void* d_out, int out_size)
{
  const int* x    = (const int*)d_in[0];
  const int* mask = (const int*)d_in[1];
  int base = (in_sizes[2] == 1) ? 3 : 2;   // skip scalar TASK if present
  const float* embed  = (const float*)d_in[base+0];
  const float* W_ih   = (const float*)d_in[base+1];
  const float* W_hh   = (const float*)d_in[base+2];
  const float* b_ih   = (const float*)d_in[base+3];
  const float* b_hh   = (const float*)d_in[base+4];
  const float* Ws_w   = (const float*)d_in[base+5];
  const float* Ws_b   = (const float*)d_in[base+6];
  const float* Us_w   = (const float*)d_in[base+7];
  const float* Us_b   = (const float*)d_in[base+8];
  const float* Wx     = (const float*)d_in[base+9];
  const float* Wh     = (const float*)d_in[base+10];
  const float* Wm     = (const float*)d_in[base+11];
  const float* b_cell = (const float*)d_in[base+12];
  const float* fc_w   = (const float*)d_in[base+13];
  const float* fc_b   = (const float*)d_in[base+14];
  float* out = (float*)d_out;
  (void)n_in; (void)out_size;

  cudaFuncSetAttribute(k_pass2, cudaFuncAttributeMaxDynamicSharedMemorySize,
                       P2_FLOATS*4);

  k_gather<<<Msz, 64>>>(x, embed);
  k_gemm<<<dim3(16,16), 256>>>(0, W_ih, b_ih, b_hh, G4H, 256, 256, 256, 0);
  k_gemm<<<dim3(16,16), 256>>>(1, Wx,   b_cell, nullptr, G4H, 256, 256, 256, 0);
  k_pass1<<<32, 512>>>(W_hh);
  k_gemm<<<dim3(16,16), 256>>>(2, Wm,   nullptr, nullptr, G4H, 256, 256, 256, 0);
  k_gemm<<<dim3(16,4),  256>>>(3, Ws_w, Ws_b,   nullptr, Hsz, 512, 256, 768, 256);
  k_pass2<<<64, 512, P2_FLOATS*4>>>(Wh, Ws_w, Us_w, Us_b, fc_w, fc_b, mask, out);
}

// round 8
// speedup vs baseline: 1.5918x; 1.0000x over previous
#include <cuda_runtime.h>
#include <cuda_bf16.h>
#include <cstdint>

#define Bsz 16
#define Ssz 64
#define Esz 256
#define Hsz 256
#define Msz (Bsz*Ssz)   /* 1024 flattened (b,s) rows */
#define G4H 1024        /* 4*H gate rows */

typedef unsigned long long ull;

// ---------------------------------------------------------------------------
// Global scratch (no allocations allowed)
// ---------------------------------------------------------------------------
__device__ float g_emb[Msz*Esz];      // emb[b,s,:]
__device__ float g_G1 [Msz*G4H];      // emb@W_ih^T + (b_ih+b_hh)
__device__ float g_Ex [Msz*G4H];      // emb@Wx^T + b_cell
__device__ float g_shared[Msz*Hsz];   // pass-1 hidden states
__device__ float g_A  [Msz*Hsz];      // shared@Ws1^T + emb@Ws3^T + Ws_b
__device__ float g_SWm[Msz*G4H];      // shared@Wm^T

// ---------------------------------------------------------------------------
// Helpers
// ---------------------------------------------------------------------------
__device__ __forceinline__ float tanha(float x){
  float r; asm("tanh.approx.f32 %0, %1;" : "=f"(r) : "f"(x)); return r;
}
__device__ __forceinline__ float sigt(float x){          // sigmoid via tanh
  return fmaf(0.5f, tanha(0.5f*x), 0.5f);
}
__device__ __forceinline__ void cluster_sync_(){
  asm volatile("barrier.cluster.arrive.aligned;" ::: "memory");
  asm volatile("barrier.cluster.wait.aligned;"   ::: "memory");
}
__device__ __forceinline__ void st_peer(void* lp, int rk, float v){
  uint32_t la = (uint32_t)__cvta_generic_to_shared(lp);
  uint32_t ra;
  asm volatile("mapa.shared::cluster.u32 %0, %1, %2;" : "=r"(ra) : "r"(la), "r"(rk));
  asm volatile("st.shared::cluster.f32 [%0], %1;" :: "r"(ra), "f"(v) : "memory");
}
__device__ __forceinline__ ull pk2(float lo, float hi){
  ull r; asm("mov.b64 %0, {%1,%2};" : "=l"(r) : "f"(lo), "f"(hi)); return r;
}
__device__ __forceinline__ void fma2(ull& acc, ull a, ull b){
  asm("fma.rn.f32x2 %0, %1, %2, %0;" : "+l"(acc) : "l"(a), "l"(b));
}
__device__ __forceinline__ float sum2(ull a){
  float lo, hi; asm("mov.b64 {%0,%1}, %2;" : "=f"(lo), "=f"(hi) : "l"(a));
  return lo + hi;
}

// ---------------------------------------------------------------------------
// K0: embedding gather.  grid = 1024 blocks, 64 threads (one float4 each)
// ---------------------------------------------------------------------------
__global__ void k_gather(const int* __restrict__ x, const float* __restrict__ embed){
  int m = blockIdx.x;
  int v = x[m];
  const float4* s = (const float4*)(embed + (size_t)v*Esz);
  float4* d = (float4*)(g_emb + (size_t)m*Esz);
  d[threadIdx.x] = s[threadIdx.x];
}

// ---------------------------------------------------------------------------
// K1: generic tiled GEMM (unchanged from R4; verified correct+adequate)
// ---------------------------------------------------------------------------
__global__ void __launch_bounds__(256) k_gemm(
    int mode, const float* __restrict__ W, const float* __restrict__ b1,
    const float* __restrict__ b2, int N, int K, int Ksplit, int ldw, int wskip)
{
  const float* X1 = (mode >= 2) ? g_shared : g_emb;
  const float* X2 = g_emb;
  float* C = (mode==0) ? g_G1 : (mode==1) ? g_Ex : (mode==2) ? g_SWm : g_A;

  __shared__ __align__(16) float Xs[16][68];
  __shared__ __align__(16) float Ws[16][68];

  int tid = threadIdx.x;
  int m0 = blockIdx.x*64, n0 = blockIdx.y*64;
  int lr = tid>>2, lc = tid&3;
  int tx = tid&15, ty = tid>>4;

  float acc[4][4];
  #pragma unroll
  for(int i=0;i<4;i++){
    #pragma unroll
    for(int j=0;j<4;j++) acc[i][j]=0.f;
  }

  for(int kt=0; kt<K; kt+=16){
    const float* xsrc = (kt < Ksplit)
        ? (X1 + (size_t)(m0+lr)*Esz + kt)
        : (X2 + (size_t)(m0+lr)*Esz + (kt-Ksplit));
    float4 xv = *(const float4*)(xsrc + lc*4);
    int kcol = kt + lc*4;
    int wc = (kcol < Ksplit) ? kcol : kcol + wskip;
    float4 wv = *(const float4*)(W + (size_t)(n0+lr)*ldw + wc);

    __syncthreads();
    Xs[lc*4+0][lr]=xv.x; Xs[lc*4+1][lr]=xv.y; Xs[lc*4+2][lr]=xv.z; Xs[lc*4+3][lr]=xv.w;
    Ws[lc*4+0][lr]=wv.x; Ws[lc*4+1][lr]=wv.y; Ws[lc*4+2][lr]=wv.z; Ws[lc*4+3][lr]=wv.w;
    __syncthreads();

    #pragma unroll
    for(int k=0;k<16;k++){
      float4 a  = *(const float4*)&Xs[k][ty*4];
      float4 bb = *(const float4*)&Ws[k][tx*4];
      acc[0][0]+=a.x*bb.x; acc[0][1]+=a.x*bb.y; acc[0][2]+=a.x*bb.z; acc[0][3]+=a.x*bb.w;
      acc[1][0]+=a.y*bb.x; acc[1][1]+=a.y*bb.y; acc[1][2]+=a.y*bb.z; acc[1][3]+=a.y*bb.w;
      acc[2][0]+=a.z*bb.x; acc[2][1]+=a.z*bb.y; acc[2][2]+=a.z*bb.z; acc[2][3]+=a.z*bb.w;
      acc[3][0]+=a.w*bb.x; acc[3][1]+=a.w*bb.y; acc[3][2]+=a.w*bb.z; acc[3][3]+=a.w*bb.w;
    }
  }

  #pragma unroll
  for(int j=0;j<4;j++){
    int n = n0 + tx*4 + j;
    float bias = (b1 ? b1[n] : 0.f) + (b2 ? b2[n] : 0.f);
    #pragma unroll
    for(int i=0;i<4;i++)
      C[(size_t)(m0+ty*4+i)*N + n] = acc[i][j] + bias;
  }
}

// ---------------------------------------------------------------------------
// K2: pass-1 shared LSTM.  Cluster of 8 CTAs; FOUR batch elements/cluster.
// grid = 32 CTAs (4 clusters).  CTA r owns h-indices [32r,32r+32).
// Thread layout: gs = tid>>8 (gate-plane: gates {0,1} or {2,3}),
//                rq = (tid>>3)&31 (row in slice), cc = tid&7 (32-wide k chunk).
// W_hh slice in registers as packed f32x2 pairs (w0/w1: 2 gates x 32 k).
// Per step: 4 batches' dots (f32x2), 3-level shfl reduce, local smem gate
// handoff, 32 producer threads do activations for all 4 batches, DSMEM h
// broadcast, ONE cluster barrier.
// ---------------------------------------------------------------------------
__global__ void __cluster_dims__(8,1,1) __launch_bounds__(512,1)
k_pass1(const float* __restrict__ W_hh)
{
  __shared__ float sh[4][2][Hsz];    // [batch][parity][h]  8 KB
  __shared__ float sGr[4][4][32];    // [batch][gate][row]  2 KB

  int cl = blockIdx.x >> 3, r = blockIdx.x & 7;
  int b0 = cl*4;
  int tid = threadIdx.x;
  int gs = tid >> 8;
  int rq = (tid >> 3) & 31;
  int cc = tid & 7;
  int gidx = r*32 + rq;
  int q0 = gs*2, q1 = gs*2 + 1;

  ull w0[16], w1[16];
  {
    const float4* s0 = (const float4*)(W_hh + (size_t)(q0*Hsz + gidx)*Hsz + cc*32);
    const float4* s1 = (const float4*)(W_hh + (size_t)(q1*Hsz + gidx)*Hsz + cc*32);
    #pragma unroll
    for(int i=0;i<8;i++){
      float4 a = s0[i]; w0[2*i] = pk2(a.x,a.y); w0[2*i+1] = pk2(a.z,a.w);
      float4 b = s1[i]; w1[2*i] = pk2(b.x,b.y); w1[2*i+1] = pk2(b.z,b.w);
    }
  }
  for(int i=tid; i<4*Hsz; i+=512){ sh[i>>8][0][i&255] = 0.f; }
  float cst[4] = {0.f,0.f,0.f,0.f};
  __syncthreads();
  cluster_sync_();   // peers' sh[*][0] initialized before anyone reads

  for(int t=0;t<Ssz;t++){
    int par = t&1;

    // prefetch gate-input terms for the 4 batches (producers only)
    float e[4][4];
    if(tid < 32){
      #pragma unroll
      for(int g=0; g<4; g++){
        const float* p = g_G1 + (size_t)((b0+g)*Ssz+t)*G4H + r*32 + tid;
        e[g][0]=p[0]; e[g][1]=p[256]; e[g][2]=p[512]; e[g][3]=p[768];
      }
    }

    // dots for 4 batches, 2 gates each (packed f32x2)
    float s0[4], s1[4];
    #pragma unroll
    for(int g=0; g<4; g++){
      const float4* hp = (const float4*)&sh[g][par][cc*32];
      ull a0 = 0ull, a1 = 0ull;
      #pragma unroll
      for(int i=0;i<8;i++){
        float4 hv = hp[i];
        ull h01 = pk2(hv.x,hv.y), h23 = pk2(hv.z,hv.w);
        fma2(a0, w0[2*i], h01); fma2(a0, w0[2*i+1], h23);
        fma2(a1, w1[2*i], h01); fma2(a1, w1[2*i+1], h23);
      }
      s0[g] = sum2(a0); s1[g] = sum2(a1);
    }
    #pragma unroll
    for(int m=1;m<8;m<<=1){
      #pragma unroll
      for(int g=0;g<4;g++){
        s0[g] += __shfl_xor_sync(0xffffffffu, s0[g], m);
        s1[g] += __shfl_xor_sync(0xffffffffu, s1[g], m);
      }
    }
    if(cc==0){
      #pragma unroll
      for(int g=0;g<4;g++){ sGr[g][q0][rq] = s0[g]; sGr[g][q1][rq] = s1[g]; }
    }
    __syncthreads();

    // producers: 32 threads, one row each, all 4 batches
    if(tid < 32){
      int p1 = (t+1)&1;
      int gx = r*32 + tid;
      #pragma unroll
      for(int g=0;g<4;g++){
        float gi = sGr[g][0][tid] + e[g][0];
        float gf = sGr[g][1][tid] + e[g][1];
        float gg = sGr[g][2][tid] + e[g][2];
        float go = sGr[g][3][tid] + e[g][3];
        cst[g] = sigt(gf)*cst[g] + sigt(gi)*tanha(gg);
        float h = sigt(go)*tanha(cst[g]);
        #pragma unroll
        for(int rk=0;rk<8;rk++) st_peer(&sh[g][p1][gx], rk, h);
        g_shared[(size_t)((b0+g)*Ssz+t)*Hsz + gx] = h;
      }
    }
    cluster_sync_();
  }
}

// ---------------------------------------------------------------------------
// K4: pass-2 task LSTM with attention.  Cluster 8; TWO batches/cluster.
// grid = 64 CTAs (8 clusters).  TWO cluster syncs per step:
//   phase a: Ws2·h (local slice!) + Wh·h dots -> local smem hW2 slice
//   phase b: j-slice Si PARTIALS for all 64 s (local A/Us/hW2 slices),
//            all-to-all exchange of 64 partials  [cluster sync #1]
//   phase c: per-CTA Si sum + masked softmax (fully local)
//   phase d: att·SWm + gates -> h broadcast     [cluster sync #2]
// Dynamic smem (~92 KB).
// ---------------------------------------------------------------------------
#define P2_SWM  0            /* [g][128][64]  2*8192  */
#define P2_A    16384        /* [g][64][32]   2*2048  */
#define P2_PART 20480        /* [g][8][64]    2*512   */
#define P2_H    21504        /* [g][2][256]   2*512   */
#define P2_W2   22528        /* [g][32]       2*32    */
#define P2_ATT  22592        /* [g][64]       2*64    */
#define P2_US   22720        /* [32]                  */
#define P2_VAL  22752        /* [g][64] ints  2*64    */
#define P2_FLOATS 22880

__global__ void __cluster_dims__(8,1,1) __launch_bounds__(512,1)
k_pass2(const float* __restrict__ Wh,   const float* __restrict__ Ws_w,
        const float* __restrict__ Us_w, const float* __restrict__ Us_b,
        const float* __restrict__ fc_w, const float* __restrict__ fc_b,
        const int*   __restrict__ mask, float* __restrict__ out)
{
  extern __shared__ __align__(16) float dsm[];
  float* sSWm = dsm + P2_SWM;
  float* sA   = dsm + P2_A;
  float* sPart= dsm + P2_PART;
  float* sh   = dsm + P2_H;
  float* sW2  = dsm + P2_W2;
  float* sAtt = dsm + P2_ATT;
  float* sUs  = dsm + P2_US;
  int*   sVal = (int*)(dsm + P2_VAL);

  int cl = blockIdx.x >> 3, r = blockIdx.x & 7;
  int b0 = cl*2;
  int tid = threadIdx.x;
  int rq = tid >> 4, cc = tid & 15;
  int lane = tid & 31, wid = tid >> 5;
  int gidx = r*32 + rq;

  // prologue loads
  for(int i=tid; i<2*128*64; i+=512){
    int g = i>>13, rem = i & 8191, row = rem>>6, s = rem&63;
    sSWm[i] = g_SWm[(size_t)((b0+g)*Ssz+s)*G4H + (row>>5)*Hsz + r*32 + (row&31)];
  }
  for(int i=tid; i<2*64*32; i+=512){
    int g = i>>11, rem = i & 2047, s = rem>>5, j = rem&31;
    sA[i] = g_A[(size_t)((b0+g)*Ssz+s)*Hsz + r*32 + j];
  }
  if(tid < 32) sUs[tid] = Us_w[r*32 + tid];
  if(tid < 128){ int g = tid>>6; sVal[tid] = mask[(b0+g)*Ssz + (tid&63)]; }
  for(int i=tid; i<2*Hsz; i+=512){ sh[(i>>8)*512 + (i&255)] = 0.f; }  // parity 0

  ull wq[4][8];
  #pragma unroll
  for(int q=0;q<4;q++){
    const float4* src = (const float4*)(Wh + (size_t)(q*Hsz + gidx)*Hsz + cc*16);
    #pragma unroll
    for(int i=0;i<4;i++){
      float4 v = src[i];
      wq[q][2*i] = pk2(v.x,v.y); wq[q][2*i+1] = pk2(v.z,v.w);
    }
  }
  ull w2[8];
  {
    const float4* src = (const float4*)(Ws_w + (size_t)gidx*768 + Hsz + cc*16);
    #pragma unroll
    for(int i=0;i<4;i++){
      float4 v = src[i];
      w2[2*i] = pk2(v.x,v.y); w2[2*i+1] = pk2(v.z,v.w);
    }
  }
  float usb = Us_b[0];
  float cst[2] = {0.f, 0.f};
  __syncthreads();
  cluster_sync_();   // peers' sh init visible

  for(int t=0;t<Ssz;t++){
    int par = t&1;

    // prefetch Ex gate terms (producers)
    float e[2][4];
    if(cc==0){
      #pragma unroll
      for(int g=0;g<2;g++){
        const float* p = g_Ex + (size_t)((b0+g)*Ssz+t)*G4H + gidx;
        e[g][0]=p[0]; e[g][1]=p[256]; e[g][2]=p[512]; e[g][3]=p[768];
      }
    }

    // phase a: Ws2·h (own slice) + Wh·h dots
    float pa[2][4], pp[2];
    #pragma unroll
    for(int g=0;g<2;g++){
      const float4* hp = (const float4*)&sh[g*512 + par*256 + cc*16];
      ull a0=0ull,a1=0ull,a2=0ull,a3=0ull,p=0ull;
      #pragma unroll
      for(int i=0;i<4;i++){
        float4 hv = hp[i];
        ull h01 = pk2(hv.x,hv.y), h23 = pk2(hv.z,hv.w);
        fma2(a0, wq[0][2*i], h01); fma2(a0, wq[0][2*i+1], h23);
        fma2(a1, wq[1][2*i], h01); fma2(a1, wq[1][2*i+1], h23);
        fma2(a2, wq[2][2*i], h01); fma2(a2, wq[2][2*i+1], h23);
        fma2(a3, wq[3][2*i], h01); fma2(a3, wq[3][2*i+1], h23);
        fma2(p,  w2[2*i],    h01); fma2(p,  w2[2*i+1],    h23);
      }
      pa[g][0]=sum2(a0); pa[g][1]=sum2(a1); pa[g][2]=sum2(a2); pa[g][3]=sum2(a3);
      pp[g]=sum2(p);
    }
    #pragma unroll
    for(int m=1;m<16;m<<=1){
      #pragma unroll
      for(int g=0;g<2;g++){
        pp[g]    += __shfl_xor_sync(0xffffffffu, pp[g],    m);
        pa[g][0] += __shfl_xor_sync(0xffffffffu, pa[g][0], m);
        pa[g][1] += __shfl_xor_sync(0xffffffffu, pa[g][1], m);
        pa[g][2] += __shfl_xor_sync(0xffffffffu, pa[g][2], m);
        pa[g][3] += __shfl_xor_sync(0xffffffffu, pa[g][3], m);
      }
    }
    if(cc==0){
      sW2[0*32+rq] = pp[0];
      sW2[1*32+rq] = pp[1];
    }
    __syncthreads();

    // phase b: Si partials over own j-slice, for ALL 64 s
    {
      int sp = tid >> 3, jc = tid & 7;
      float P[2];
      #pragma unroll
      for(int g=0;g<2;g++){
        float acc = 0.f;
        #pragma unroll
        for(int k=0;k<4;k++){
          int j = jc*4 + k;
          acc += sUs[j] * tanha(sA[g*2048 + sp*32 + j] + sW2[g*32 + j]);
        }
        P[g] = acc;
      }
      #pragma unroll
      for(int m=1;m<8;m<<=1){
        P[0] += __shfl_xor_sync(0xffffffffu, P[0], m);
        P[1] += __shfl_xor_sync(0xffffffffu, P[1], m);
      }
      if(jc==0){
        #pragma unroll
        for(int g=0;g<2;g++){
          #pragma unroll
          for(int rk=0;rk<8;rk++) st_peer(&sPart[g*512 + r*64 + sp], rk, P[g]);
        }
      }
    }
    cluster_sync_();   // #1: all partials landed everywhere

    // phase c: Si sum + masked softmax, fully local (warp g handles batch g)
    if(wid < 2){
      int g = wid;
      float t0 = usb, t1 = usb;
      #pragma unroll
      for(int rr=0;rr<8;rr++){
        t0 += sPart[g*512 + rr*64 + lane];
        t1 += sPart[g*512 + rr*64 + lane + 32];
      }
      float v0 = sVal[g*64+lane]    ? t0 : -1e9f;
      float v1 = sVal[g*64+lane+32] ? t1 : -1e9f;
      float mx = fmaxf(v0,v1);
      #pragma unroll
      for(int m=16;m>=1;m>>=1) mx = fmaxf(mx, __shfl_xor_sync(0xffffffffu,mx,m));
      float x0 = __expf(v0-mx), x1 = __expf(v1-mx);
      float sm = x0+x1;
      #pragma unroll
      for(int m=16;m>=1;m>>=1) sm += __shfl_xor_sync(0xffffffffu,sm,m);
      float inv = __fdividef(1.f, sm);
      sAtt[g*64+lane]    = x0*inv;
      sAtt[g*64+lane+32] = x1*inv;
    }
    __syncthreads();

    // phase d: att·SWm + gates + h broadcast
    {
      float pb[2][4];
      #pragma unroll
      for(int g=0;g<2;g++){
        float4 av = *(const float4*)&sAtt[g*64 + cc*4];
        #pragma unroll
        for(int q=0;q<4;q++){
          float4 v = *(const float4*)&sSWm[g*8192 + (q*32+rq)*64 + cc*4];
          pb[g][q] = v.x*av.x + v.y*av.y + v.z*av.z + v.w*av.w;
        }
      }
      #pragma unroll
      for(int m=1;m<16;m<<=1){
        #pragma unroll
        for(int g=0;g<2;g++){
          pb[g][0] += __shfl_xor_sync(0xffffffffu, pb[g][0], m);
          pb[g][1] += __shfl_xor_sync(0xffffffffu, pb[g][1], m);
          pb[g][2] += __shfl_xor_sync(0xffffffffu, pb[g][2], m);
          pb[g][3] += __shfl_xor_sync(0xffffffffu, pb[g][3], m);
        }
      }
      if(cc==0){
        int p1 = (t+1)&1;
        #pragma unroll
        for(int g=0;g<2;g++){
          float gi = pa[g][0] + pb[g][0] + e[g][0];
          float gf = pa[g][1] + pb[g][1] + e[g][1];
          float gg = pa[g][2] + pb[g][2] + e[g][2];
          float go = pa[g][3] + pb[g][3] + e[g][3];
          cst[g] = sigt(gf)*cst[g] + sigt(gi)*tanha(gg);
          float h = sigt(go)*tanha(cst[g]);
          #pragma unroll
          for(int rk=0;rk<8;rk++) st_peer(&sh[g*512 + p1*256 + gidx], rk, h);
        }
      }
    }
    cluster_sync_();   // #2: h(t+1) landed everywhere
  }

  // final classifier (final h is in parity 0 after 64 steps)
  if(r==0 && wid < 2){
    int g = wid;
    float acc = 0.f;
    #pragma unroll
    for(int jj=0;jj<8;jj++) acc += fc_w[jj*32+lane] * sh[g*512 + jj*32 + lane];
    #pragma unroll
    for(int m=16;m>=1;m>>=1) acc += __shfl_xor_sync(0xffffffffu,acc,m);
    if(lane==0) out[b0+g] = sigt(acc + fc_b[0]);
  }
}

// ---------------------------------------------------------------------------
// Launch
// ---------------------------------------------------------------------------
extern "C" void kernel_launch(void* const* d_in, const int* in_sizes, int n_in,
                              void* d_out, int out_size)
{
  const int* x    = (const int*)d_in[0];
  const int* mask = (const int*)d_in[1];
  int base = (in_sizes[2] == 1) ? 3 : 2;   // skip scalar TASK if present
  const float* embed  = (const float*)d_in[base+0];
  const float* W_ih   = (const float*)d_in[base+1];
  const float* W_hh   = (const float*)d_in[base+2];
  const float* b_ih   = (const float*)d_in[base+3];
  const float* b_hh   = (const float*)d_in[base+4];
  const float* Ws_w   = (const float*)d_in[base+5];
  const float* Ws_b   = (const float*)d_in[base+6];
  const float* Us_w   = (const float*)d_in[base+7];
  const float* Us_b   = (const float*)d_in[base+8];
  const float* Wx     = (const float*)d_in[base+9];
  const float* Wh     = (const float*)d_in[base+10];
  const float* Wm     = (const float*)d_in[base+11];
  const float* b_cell = (const float*)d_in[base+12];
  const float* fc_w   = (const float*)d_in[base+13];
  const float* fc_b   = (const float*)d_in[base+14];
  float* out = (float*)d_out;
  (void)n_in; (void)out_size;

  cudaFuncSetAttribute(k_pass2, cudaFuncAttributeMaxDynamicSharedMemorySize,
                       P2_FLOATS*4);

  k_gather<<<Msz, 64>>>(x, embed);
  k_gemm<<<dim3(16,16), 256>>>(0, W_ih, b_ih, b_hh, G4H, 256, 256, 256, 0);
  k_gemm<<<dim3(16,16), 256>>>(1, Wx,   b_cell, nullptr, G4H, 256, 256, 256, 0);
  k_pass1<<<32, 512>>>(W_hh);
  k_gemm<<<dim3(16,16), 256>>>(2, Wm,   nullptr, nullptr, G4H, 256, 256, 256, 0);
  k_gemm<<<dim3(16,4),  256>>>(3, Ws_w, Ws_b,   nullptr, Hsz, 512, 256, 768, 256);
  k_pass2<<<64, 512, P2_FLOATS*4>>>(Wh, Ws_w, Us_w, Us_b, fc_w, fc_b, mask, out);
}